// round 1
// baseline (speedup 1.0000x reference)
#include <cuda_runtime.h>
#include <math.h>

// Problem dims (fixed)
#define BB   4
#define TT   2048
#define DD   1024
#define HH   16
#define HSV  64
#define FF   4096
#define BT   (BB*TT)          // 8192 rows

// ---------------- scratch (device globals; no runtime allocation) ----------
__device__ float g_xn [BT*DD];   // LN output (reused for LN2)
__device__ float g_q  [BT*DD];
__device__ float g_k  [BT*DD];
__device__ float g_v  [BT*DD];
__device__ float g_ctx[BT*DD];
__device__ float g_x1 [BT*DD];   // after attention residual
__device__ float g_h  [BT*FF];   // FFN hidden
__device__ float g_wt [3*DD*DD]; // repacked wq/wk/wv -> [D, H*HS]

// ---------------- weight repack: [H,D,HS] -> [D, H*HS] row-major -----------
__global__ void repack_w(const float* __restrict__ w, float* __restrict__ out) {
    int idx = blockIdx.x * 256 + threadIdx.x;   // 0 .. 1024*1024-1
    int d = idx >> 10;
    int n = idx & 1023;
    int h = n >> 6, kk = n & 63;
    out[idx] = w[h * (DD * HSV) + d * HSV + kk];
}

// ---------------- layernorm: one block per row ------------------------------
__global__ void ln_kernel(const float* __restrict__ x, const float* __restrict__ g,
                          const float* __restrict__ b, float* __restrict__ out) {
    int row = blockIdx.x;
    const float* xr = x + (size_t)row * DD;
    float vv[4];
    float s = 0.f, sq = 0.f;
#pragma unroll
    for (int i = 0; i < 4; i++) {
        float t = xr[threadIdx.x + i * 256];
        vv[i] = t; s += t; sq += t * t;
    }
    __shared__ float red[64];
#pragma unroll
    for (int o = 16; o > 0; o >>= 1) {
        s  += __shfl_xor_sync(0xffffffffu, s, o);
        sq += __shfl_xor_sync(0xffffffffu, sq, o);
    }
    int warp = threadIdx.x >> 5, lane = threadIdx.x & 31;
    if (lane == 0) { red[warp] = s; red[warp + 8] = sq; }
    __syncthreads();
    if (threadIdx.x < 32) {
        float ss = (threadIdx.x < 8) ? red[threadIdx.x] : 0.f;
        float qq = (threadIdx.x < 8) ? red[threadIdx.x + 8] : 0.f;
#pragma unroll
        for (int o = 4; o > 0; o >>= 1) {
            ss += __shfl_xor_sync(0xffffffffu, ss, o);
            qq += __shfl_xor_sync(0xffffffffu, qq, o);
        }
        if (threadIdx.x == 0) { red[32] = ss; red[33] = qq; }
    }
    __syncthreads();
    float mean = red[32] * (1.f / DD);
    float var  = red[33] * (1.f / DD) - mean * mean;
    float inv  = rsqrtf(var + 1e-5f);
#pragma unroll
    for (int i = 0; i < 4; i++) {
        int c = threadIdx.x + i * 256;
        out[(size_t)row * DD + c] = (vv[i] - mean) * inv * g[c] + b[c];
    }
}

// ---------------- fp32 tiled GEMM: C = A[MxK] @ B[KxN] (+bias)(+relu)(+res) -
// 64x64 tile, BK=16, 256 threads, 4x4 micro-tile per thread.
template<bool RELU, bool BIAS, bool RES>
__global__ void gemm64(const float* __restrict__ A, const float* __restrict__ B,
                       const float* __restrict__ bias, const float* __restrict__ res,
                       float* __restrict__ C, int M, int N, int K) {
    __shared__ float As[16][64];
    __shared__ float Bs[16][64];
    int t  = threadIdx.x;
    int tx = t & 15, ty = t >> 4;
    int m0 = blockIdx.y * 64, n0 = blockIdx.x * 64;
    int arow = t >> 2, akv = t & 3;     // A tile load
    int brow = t >> 4, bnv = t & 15;    // B tile load
    float acc[4][4] = {};
    for (int k0 = 0; k0 < K; k0 += 16) {
        float4 a = *(const float4*)(A + (size_t)(m0 + arow) * K + k0 + akv * 4);
        As[akv * 4 + 0][arow] = a.x;
        As[akv * 4 + 1][arow] = a.y;
        As[akv * 4 + 2][arow] = a.z;
        As[akv * 4 + 3][arow] = a.w;
        *(float4*)&Bs[brow][bnv * 4] =
            *(const float4*)(B + (size_t)(k0 + brow) * N + n0 + bnv * 4);
        __syncthreads();
#pragma unroll
        for (int kk = 0; kk < 16; kk++) {
            float4 av = *(const float4*)&As[kk][ty * 4];
            float4 bv = *(const float4*)&Bs[kk][tx * 4];
            float aa[4] = {av.x, av.y, av.z, av.w};
            float bb[4] = {bv.x, bv.y, bv.z, bv.w};
#pragma unroll
            for (int i = 0; i < 4; i++)
#pragma unroll
                for (int j = 0; j < 4; j++)
                    acc[i][j] += aa[i] * bb[j];
        }
        __syncthreads();
    }
#pragma unroll
    for (int i = 0; i < 4; i++) {
        int gm = m0 + ty * 4 + i;
#pragma unroll
        for (int j = 0; j < 4; j++) {
            int gn = n0 + tx * 4 + j;
            float v = acc[i][j];
            if (BIAS) v += bias[gn];
            if (RELU) v = fmaxf(v, 0.f);
            if (RES)  v += res[(size_t)gm * N + gn];
            C[(size_t)gm * N + gn] = v;
        }
    }
}

// ---------------- causal flash attention, fp32, 64x64 tiles -----------------
// q,k,v,ctx layout: [(b*T + t)*D + h*64 + e]
__global__ void attn_kernel(const float* __restrict__ q, const float* __restrict__ k,
                            const float* __restrict__ v, float* __restrict__ ctx) {
    extern __shared__ float sm[];
    float* Qs   = sm;            // 64*64
    float* KVs  = sm + 4096;     // 64*64 (K then V)
    float* Ss   = sm + 8192;     // 64*64
    float* mrow = sm + 12288;    // 64
    float* lrow = mrow + 64;     // 64
    float* frow = lrow + 64;     // 64

    int qt = blockIdx.x;                 // query tile 0..31
    int bh = blockIdx.y;                 // 0..63
    int b = bh / HH, h = bh % HH;
    int t0 = qt * 64;
    int tid = threadIdx.x;
    int tx = tid & 15, ty = tid >> 4;

    const float* qbase = q + (size_t)b * TT * DD + h * HSV;
    const float* kbase = k + (size_t)b * TT * DD + h * HSV;
    const float* vbase = v + (size_t)b * TT * DD + h * HSV;

    // load Q tile (row r, 64 floats each)
#pragma unroll
    for (int it = 0; it < 4; it++) {
        int f = tid + it * 256;          // float4 idx 0..1023
        int r = f >> 4, c4 = f & 15;
        *(float4*)&Qs[r * 64 + c4 * 4] =
            *(const float4*)(qbase + (size_t)(t0 + r) * DD + c4 * 4);
    }
    if (tid < 64) { mrow[tid] = -INFINITY; lrow[tid] = 0.f; }
    float o[4][4] = {};
    __syncthreads();

    for (int jt = 0; jt <= qt; jt++) {
        // load K tile
#pragma unroll
        for (int it = 0; it < 4; it++) {
            int f = tid + it * 256; int r = f >> 4, c4 = f & 15;
            *(float4*)&KVs[r * 64 + c4 * 4] =
                *(const float4*)(kbase + (size_t)(jt * 64 + r) * DD + c4 * 4);
        }
        __syncthreads();

        // S = (Q K^T) * scale, causal mask on diagonal tile
        float s[4][4] = {};
#pragma unroll
        for (int kv = 0; kv < 16; kv++) {
            float4 qv[4], kvv[4];
#pragma unroll
            for (int i = 0; i < 4; i++)
                qv[i] = *(const float4*)&Qs[(ty * 4 + i) * 64 + kv * 4];
#pragma unroll
            for (int j = 0; j < 4; j++)
                kvv[j] = *(const float4*)&KVs[(tx * 4 + j) * 64 + kv * 4];
#pragma unroll
            for (int i = 0; i < 4; i++)
#pragma unroll
                for (int j = 0; j < 4; j++)
                    s[i][j] += qv[i].x * kvv[j].x + qv[i].y * kvv[j].y
                             + qv[i].z * kvv[j].z + qv[i].w * kvv[j].w;
        }
        bool diag = (jt == qt);
#pragma unroll
        for (int i = 0; i < 4; i++) {
            int r = ty * 4 + i;
#pragma unroll
            for (int j = 0; j < 4; j++) {
                int c = tx * 4 + j;
                float val = s[i][j] * 0.125f;
                if (diag && c > r) val = -INFINITY;
                Ss[r * 64 + c] = val;
            }
        }
        __syncthreads();   // K reads done; Ss visible

        // load V tile (overwrites K) — independent of softmax on Ss
#pragma unroll
        for (int it = 0; it < 4; it++) {
            int f = tid + it * 256; int r = f >> 4, c4 = f & 15;
            *(float4*)&KVs[r * 64 + c4 * 4] =
                *(const float4*)(vbase + (size_t)(jt * 64 + r) * DD + c4 * 4);
        }

        // online softmax row update: 4 threads per row
        {
            int r = tid >> 2, qq = tid & 3;
            float mx = -INFINITY;
#pragma unroll
            for (int c = 0; c < 16; c++)
                mx = fmaxf(mx, Ss[r * 64 + qq * 16 + c]);
            mx = fmaxf(mx, __shfl_xor_sync(0xffffffffu, mx, 1));
            mx = fmaxf(mx, __shfl_xor_sync(0xffffffffu, mx, 2));
            float mold = mrow[r];
            float mnew = fmaxf(mold, mx);
            float sum = 0.f;
#pragma unroll
            for (int c = 0; c < 16; c++) {
                float p = __expf(Ss[r * 64 + qq * 16 + c] - mnew);
                Ss[r * 64 + qq * 16 + c] = p;
                sum += p;
            }
            sum += __shfl_xor_sync(0xffffffffu, sum, 1);
            sum += __shfl_xor_sync(0xffffffffu, sum, 2);
            if (qq == 0) {
                float fac = __expf(mold - mnew);   // mold=-inf -> 0
                lrow[r] = lrow[r] * fac + sum;
                mrow[r] = mnew;
                frow[r] = fac;
            }
        }
        __syncthreads();

        // rescale O and accumulate O += P @ V
        float fi[4];
#pragma unroll
        for (int i = 0; i < 4; i++) fi[i] = frow[ty * 4 + i];
#pragma unroll
        for (int i = 0; i < 4; i++)
#pragma unroll
            for (int j = 0; j < 4; j++) o[i][j] *= fi[i];
#pragma unroll
        for (int jj = 0; jj < 64; jj++) {
            float4 vv4 = *(const float4*)&KVs[jj * 64 + tx * 4];
            float pi[4];
#pragma unroll
            for (int i = 0; i < 4; i++) pi[i] = Ss[(ty * 4 + i) * 64 + jj];
#pragma unroll
            for (int i = 0; i < 4; i++) {
                o[i][0] += pi[i] * vv4.x;
                o[i][1] += pi[i] * vv4.y;
                o[i][2] += pi[i] * vv4.z;
                o[i][3] += pi[i] * vv4.w;
            }
        }
        __syncthreads();   // protect KVs/Ss for next iter
    }

    // normalize + write ctx
    float inv[4];
#pragma unroll
    for (int i = 0; i < 4; i++) inv[i] = 1.f / lrow[ty * 4 + i];
#pragma unroll
    for (int i = 0; i < 4; i++) {
        int r = t0 + ty * 4 + i;
        float4 ov;
        ov.x = o[i][0] * inv[i]; ov.y = o[i][1] * inv[i];
        ov.z = o[i][2] * inv[i]; ov.w = o[i][3] * inv[i];
        *(float4*)(ctx + (size_t)(b * TT + r) * DD + h * HSV + tx * 4) = ov;
    }
}

// ---------------- launcher --------------------------------------------------
extern "C" void kernel_launch(void* const* d_in, const int* in_sizes, int n_in,
                              void* d_out, int out_size) {
    const float* x      = (const float*)d_in[0];
    const float* ln1_g  = (const float*)d_in[1];
    const float* ln1_b  = (const float*)d_in[2];
    const float* wq     = (const float*)d_in[3];
    const float* wk     = (const float*)d_in[4];
    const float* wv     = (const float*)d_in[5];
    const float* w_proj = (const float*)d_in[6];
    const float* b_proj = (const float*)d_in[7];
    const float* ln2_g  = (const float*)d_in[8];
    const float* ln2_b  = (const float*)d_in[9];
    const float* w1     = (const float*)d_in[10];
    const float* b1     = (const float*)d_in[11];
    const float* w2     = (const float*)d_in[12];
    const float* b2     = (const float*)d_in[13];
    float* out = (float*)d_out;

    float *xn, *qb, *kb, *vb, *ctx, *x1, *hb, *wt;
    cudaGetSymbolAddress((void**)&xn,  g_xn);
    cudaGetSymbolAddress((void**)&qb,  g_q);
    cudaGetSymbolAddress((void**)&kb,  g_k);
    cudaGetSymbolAddress((void**)&vb,  g_v);
    cudaGetSymbolAddress((void**)&ctx, g_ctx);
    cudaGetSymbolAddress((void**)&x1,  g_x1);
    cudaGetSymbolAddress((void**)&hb,  g_h);
    cudaGetSymbolAddress((void**)&wt,  g_wt);
    float* wqt = wt;
    float* wkt = wt + DD * DD;
    float* wvt = wt + 2 * DD * DD;

    // repack per-head QKV weights into [D, H*HS]
    repack_w<<<4096, 256>>>(wq, wqt);
    repack_w<<<4096, 256>>>(wk, wkt);
    repack_w<<<4096, 256>>>(wv, wvt);

    // LN1
    ln_kernel<<<BT, 256>>>(x, ln1_g, ln1_b, xn);

    // QKV projections
    dim3 gq(DD / 64, BT / 64);
    gemm64<false, false, false><<<gq, 256>>>(xn, wqt, nullptr, nullptr, qb, BT, DD, DD);
    gemm64<false, false, false><<<gq, 256>>>(xn, wkt, nullptr, nullptr, kb, BT, DD, DD);
    gemm64<false, false, false><<<gq, 256>>>(xn, wvt, nullptr, nullptr, vb, BT, DD, DD);

    // attention
    static int smem_set = 0;
    (void)smem_set;
    cudaFuncSetAttribute(attn_kernel, cudaFuncAttributeMaxDynamicSharedMemorySize, 49920);
    attn_kernel<<<dim3(TT / 64, BB * HH), 256, 49920>>>(qb, kb, vb, ctx);

    // output projection + residual
    gemm64<false, true, true><<<gq, 256>>>(ctx, w_proj, b_proj, x, x1, BT, DD, DD);

    // LN2 (reuse xn)
    ln_kernel<<<BT, 256>>>(x1, ln2_g, ln2_b, xn);

    // FFN
    gemm64<true, true, false><<<dim3(FF / 64, BT / 64), 256>>>(xn, w1, b1, nullptr, hb, BT, FF, DD);
    gemm64<false, true, true><<<gq, 256>>>(hb, w2, b2, x1, out, BT, DD, FF);
}

// round 3
// speedup vs baseline: 2.0219x; 2.0219x over previous
#include <cuda_runtime.h>
#include <math.h>
#include <stdint.h>

#define BB   4
#define TT   2048
#define DD   1024
#define HH   16
#define HSV  64
#define FF   4096
#define BT   (BB*TT)
#define QLD  (3*DD)          // packed qkv row stride

// ---------------- scratch (device globals; no runtime allocation) ----------
__device__ float g_xn [BT*DD];
__device__ float g_qkv[BT*3*DD];
__device__ float g_ctx[BT*DD];
__device__ float g_x1 [BT*DD];
__device__ float g_h  [(size_t)BT*FF];
__device__ float g_w  [12*1024*1024];   // qkv' 3M | proj' 1M | w1' 4M | w2' 4M

// ---------------- small helpers --------------------------------------------
__device__ __forceinline__ uint32_t s2u(const void* p) {
    return (uint32_t)__cvta_generic_to_shared(p);
}
__device__ __forceinline__ float rnd_tf32(float x) {
    uint32_t u;
    asm("cvt.rna.tf32.f32 %0, %1;" : "=r"(u) : "f"(x));
    return __uint_as_float(u);
}
__device__ __forceinline__ void mma_tf32(float* c, const uint32_t* a, const uint32_t* b) {
    asm volatile(
        "mma.sync.aligned.m16n8k8.row.col.f32.tf32.tf32.f32 "
        "{%0,%1,%2,%3}, {%4,%5,%6,%7}, {%8,%9}, {%0,%1,%2,%3};"
        : "+f"(c[0]), "+f"(c[1]), "+f"(c[2]), "+f"(c[3])
        : "r"(a[0]), "r"(a[1]), "r"(a[2]), "r"(a[3]), "r"(b[0]), "r"(b[1]));
}
#define CP_COMMIT() asm volatile("cp.async.commit_group;" ::: "memory")
template<int N> __device__ __forceinline__ void cp_wait() {
    asm volatile("cp.async.wait_group %0;" :: "n"(N) : "memory");
}

// ---------------- weight repack kernels (with tf32 rounding) ---------------
// wq/wk/wv: [H, D, HS] -> out rows n=h*64+j, cols d  ([1024, 1024] K-major)
__global__ void transpose_qkv(const float* __restrict__ w, float* __restrict__ out) {
    __shared__ float sm_[32][33];
    int d0 = blockIdx.x * 32, j0 = blockIdx.y * 32, h = blockIdx.z;
    sm_[threadIdx.y][threadIdx.x] =
        w[((size_t)h * DD + d0 + threadIdx.y) * HSV + j0 + threadIdx.x];
    __syncthreads();
    out[(size_t)(h * HSV + j0 + threadIdx.y) * DD + d0 + threadIdx.x] =
        rnd_tf32(sm_[threadIdx.x][threadIdx.y]);
}
// in [K, N] row-major -> out [N, K] row-major
__global__ void transpose_mat(const float* __restrict__ in, float* __restrict__ out,
                              int K, int N) {
    __shared__ float sm_[32][33];
    int n0 = blockIdx.x * 32, k0 = blockIdx.y * 32;
    sm_[threadIdx.y][threadIdx.x] = in[(size_t)(k0 + threadIdx.y) * N + n0 + threadIdx.x];
    __syncthreads();
    out[(size_t)(n0 + threadIdx.y) * K + k0 + threadIdx.x] =
        rnd_tf32(sm_[threadIdx.x][threadIdx.y]);
}

// ---------------- layernorm (tf32-rounded output) ---------------------------
__global__ void ln_kernel(const float* __restrict__ x, const float* __restrict__ g,
                          const float* __restrict__ b, float* __restrict__ out) {
    int row = blockIdx.x;
    const float* xr = x + (size_t)row * DD;
    float vv[4];
    float s = 0.f, sq = 0.f;
#pragma unroll
    for (int i = 0; i < 4; i++) {
        float t = xr[threadIdx.x + i * 256];
        vv[i] = t; s += t; sq += t * t;
    }
    __shared__ float red[64];
#pragma unroll
    for (int o = 16; o > 0; o >>= 1) {
        s  += __shfl_xor_sync(0xffffffffu, s, o);
        sq += __shfl_xor_sync(0xffffffffu, sq, o);
    }
    int warp = threadIdx.x >> 5, lane = threadIdx.x & 31;
    if (lane == 0) { red[warp] = s; red[warp + 8] = sq; }
    __syncthreads();
    if (threadIdx.x < 32) {
        float ss = (threadIdx.x < 8) ? red[threadIdx.x] : 0.f;
        float qq = (threadIdx.x < 8) ? red[threadIdx.x + 8] : 0.f;
#pragma unroll
        for (int o = 4; o > 0; o >>= 1) {
            ss += __shfl_xor_sync(0xffffffffu, ss, o);
            qq += __shfl_xor_sync(0xffffffffu, qq, o);
        }
        if (threadIdx.x == 0) { red[32] = ss; red[33] = qq; }
    }
    __syncthreads();
    float mean = red[32] * (1.f / DD);
    float var  = red[33] * (1.f / DD) - mean * mean;
    float inv  = rsqrtf(var + 1e-5f);
#pragma unroll
    for (int i = 0; i < 4; i++) {
        int c = threadIdx.x + i * 256;
        out[(size_t)row * DD + c] = rnd_tf32((vv[i] - mean) * inv * g[c] + b[c]);
    }
}

// ---------------- mma.sync tf32 GEMM: C = A[MxK] @ Bt[NxK]^T ----------------
// 128x128 tile, BK=32, 3-stage cp.async, 8 warps (2x4), 64x32 warp tiles.
#define GS 3
#define SPITCH 36                    // padded floats per 32-col row
#define STGF (2*128*SPITCH)          // floats per stage (A+B)

__device__ __forceinline__ void ld_stage(float* sA, const float* Ag, const float* Bg,
                                         int K, int tid) {
#pragma unroll
    for (int i = 0; i < 4; i++) {
        int j = tid + (i << 8);
        int r = j >> 3, q = j & 7;
        uint32_t dst = s2u(sA + r * SPITCH + q * 4);
        asm volatile("cp.async.cg.shared.global [%0], [%1], 16;"
                     :: "r"(dst), "l"(Ag + (size_t)r * K + q * 4) : "memory");
    }
    float* sB = sA + 128 * SPITCH;
#pragma unroll
    for (int i = 0; i < 4; i++) {
        int j = tid + (i << 8);
        int r = j >> 3, q = j & 7;
        uint32_t dst = s2u(sB + r * SPITCH + q * 4);
        asm volatile("cp.async.cg.shared.global [%0], [%1], 16;"
                     :: "r"(dst), "l"(Bg + (size_t)r * K + q * 4) : "memory");
    }
}

template<bool BIAS, bool RELU, bool RES, bool ROUND>
__global__ __launch_bounds__(256, 2)
void tc_gemm(const float* __restrict__ A, const float* __restrict__ Bt,
             const float* __restrict__ bias, const float* __restrict__ res,
             float* __restrict__ C, int M, int N, int K) {
    extern __shared__ float sm[];
    int tid = threadIdx.x, wid = tid >> 5, lane = tid & 31;
    int wm = wid >> 2, wn = wid & 3;          // warp grid 2(M) x 4(N)
    int g = lane >> 2, tig = lane & 3;
    int n0 = blockIdx.x * 128, m0 = blockIdx.y * 128;

    const float* Ab = A + (size_t)m0 * K;
    const float* Bb = Bt + (size_t)n0 * K;
    int nch = K >> 5;

    float acc[4][4][4] = {};

    // prologue
#pragma unroll
    for (int c = 0; c < GS; c++) {
        ld_stage(sm + c * STGF, Ab + c * 32, Bb + c * 32, K, tid);
        CP_COMMIT();
    }

    for (int c = 0; c < nch; c++) {
        cp_wait<GS - 1>();
        __syncthreads();
        float* sA = sm + (c % GS) * STGF;
        float* sB = sA + 128 * SPITCH;
        const uint32_t* uA = (const uint32_t*)sA;
        const uint32_t* uB = (const uint32_t*)sB;
#pragma unroll
        for (int kk = 0; kk < 4; kk++) {
            int kb = kk * 8;
            uint32_t af[4][4], bf[4][2];
#pragma unroll
            for (int i = 0; i < 4; i++) {
                int r = wm * 64 + i * 16 + g;
                af[i][0] = uA[r * SPITCH + kb + tig];
                af[i][1] = uA[(r + 8) * SPITCH + kb + tig];
                af[i][2] = uA[r * SPITCH + kb + tig + 4];
                af[i][3] = uA[(r + 8) * SPITCH + kb + tig + 4];
            }
#pragma unroll
            for (int j = 0; j < 4; j++) {
                int nrow = wn * 32 + j * 8 + g;
                bf[j][0] = uB[nrow * SPITCH + kb + tig];
                bf[j][1] = uB[nrow * SPITCH + kb + tig + 4];
            }
#pragma unroll
            for (int i = 0; i < 4; i++)
#pragma unroll
                for (int j = 0; j < 4; j++)
                    mma_tf32(acc[i][j], af[i], bf[j]);
        }
        __syncthreads();
        if (c + GS < nch)
            ld_stage(sA, Ab + (size_t)(c + GS) * 32, Bb + (size_t)(c + GS) * 32, K, tid);
        CP_COMMIT();
    }

    // epilogue
#pragma unroll
    for (int i = 0; i < 4; i++) {
        int m_up = m0 + wm * 64 + i * 16 + g;
#pragma unroll
        for (int j = 0; j < 4; j++) {
            int n = n0 + wn * 32 + j * 8 + 2 * tig;
            float v0 = acc[i][j][0], v1 = acc[i][j][1];
            float v2 = acc[i][j][2], v3 = acc[i][j][3];
            if (BIAS) {
                float2 bv = *(const float2*)(bias + n);
                v0 += bv.x; v1 += bv.y; v2 += bv.x; v3 += bv.y;
            }
            if (RELU) {
                v0 = fmaxf(v0, 0.f); v1 = fmaxf(v1, 0.f);
                v2 = fmaxf(v2, 0.f); v3 = fmaxf(v3, 0.f);
            }
            if (RES) {
                float2 r0 = *(const float2*)(res + (size_t)m_up * N + n);
                float2 r1 = *(const float2*)(res + (size_t)(m_up + 8) * N + n);
                v0 += r0.x; v1 += r0.y; v2 += r1.x; v3 += r1.y;
            }
            if (ROUND) {
                v0 = rnd_tf32(v0); v1 = rnd_tf32(v1);
                v2 = rnd_tf32(v2); v3 = rnd_tf32(v3);
            }
            *(float2*)(C + (size_t)m_up * N + n) = make_float2(v0, v1);
            *(float2*)(C + (size_t)(m_up + 8) * N + n) = make_float2(v2, v3);
        }
    }
}

// ---------------- causal flash attention, fp32, 64x64 tiles -----------------
// packed qkv layout: row (b*T+t), stride QLD; q at +h*64, k at +1024+h*64, v at +2048+h*64
__global__ void attn_kernel(const float* __restrict__ qkv, float* __restrict__ ctx) {
    extern __shared__ float sm[];
    float* Qs   = sm;
    float* KVs  = sm + 4096;
    float* Ss   = sm + 8192;
    float* mrow = sm + 12288;
    float* lrow = mrow + 64;
    float* frow = lrow + 64;

    int qt = blockIdx.x;
    int bh = blockIdx.y;
    int b = bh / HH, h = bh % HH;
    int t0 = qt * 64;
    int tid = threadIdx.x;
    int tx = tid & 15, ty = tid >> 4;

    const float* qbase = qkv + (size_t)b * TT * QLD + h * HSV;
    const float* kbase = qbase + DD;
    const float* vbase = qbase + 2 * DD;

#pragma unroll
    for (int it = 0; it < 4; it++) {
        int f = tid + it * 256;
        int r = f >> 4, c4 = f & 15;
        *(float4*)&Qs[r * 64 + c4 * 4] =
            *(const float4*)(qbase + (size_t)(t0 + r) * QLD + c4 * 4);
    }
    if (tid < 64) { mrow[tid] = -INFINITY; lrow[tid] = 0.f; }
    float o[4][4] = {};
    __syncthreads();

    for (int jt = 0; jt <= qt; jt++) {
#pragma unroll
        for (int it = 0; it < 4; it++) {
            int f = tid + it * 256; int r = f >> 4, c4 = f & 15;
            *(float4*)&KVs[r * 64 + c4 * 4] =
                *(const float4*)(kbase + (size_t)(jt * 64 + r) * QLD + c4 * 4);
        }
        __syncthreads();

        float s[4][4] = {};
#pragma unroll
        for (int kv = 0; kv < 16; kv++) {
            float4 qv[4], kvv[4];
#pragma unroll
            for (int i = 0; i < 4; i++)
                qv[i] = *(const float4*)&Qs[(ty * 4 + i) * 64 + kv * 4];
#pragma unroll
            for (int j = 0; j < 4; j++)
                kvv[j] = *(const float4*)&KVs[(tx * 4 + j) * 64 + kv * 4];
#pragma unroll
            for (int i = 0; i < 4; i++)
#pragma unroll
                for (int j = 0; j < 4; j++)
                    s[i][j] += qv[i].x * kvv[j].x + qv[i].y * kvv[j].y
                             + qv[i].z * kvv[j].z + qv[i].w * kvv[j].w;
        }
        bool diag = (jt == qt);
#pragma unroll
        for (int i = 0; i < 4; i++) {
            int r = ty * 4 + i;
#pragma unroll
            for (int j = 0; j < 4; j++) {
                int c = tx * 4 + j;
                float val = s[i][j] * 0.125f;
                if (diag && c > r) val = -INFINITY;
                Ss[r * 64 + c] = val;
            }
        }
        __syncthreads();

#pragma unroll
        for (int it = 0; it < 4; it++) {
            int f = tid + it * 256; int r = f >> 4, c4 = f & 15;
            *(float4*)&KVs[r * 64 + c4 * 4] =
                *(const float4*)(vbase + (size_t)(jt * 64 + r) * QLD + c4 * 4);
        }

        {
            int r = tid >> 2, qq = tid & 3;
            float mx = -INFINITY;
#pragma unroll
            for (int c = 0; c < 16; c++)
                mx = fmaxf(mx, Ss[r * 64 + qq * 16 + c]);
            mx = fmaxf(mx, __shfl_xor_sync(0xffffffffu, mx, 1));
            mx = fmaxf(mx, __shfl_xor_sync(0xffffffffu, mx, 2));
            float mold = mrow[r];
            float mnew = fmaxf(mold, mx);
            float sum = 0.f;
#pragma unroll
            for (int c = 0; c < 16; c++) {
                float p = __expf(Ss[r * 64 + qq * 16 + c] - mnew);
                Ss[r * 64 + qq * 16 + c] = p;
                sum += p;
            }
            sum += __shfl_xor_sync(0xffffffffu, sum, 1);
            sum += __shfl_xor_sync(0xffffffffu, sum, 2);
            if (qq == 0) {
                float fac = __expf(mold - mnew);
                lrow[r] = lrow[r] * fac + sum;
                mrow[r] = mnew;
                frow[r] = fac;
            }
        }
        __syncthreads();

        float fi[4];
#pragma unroll
        for (int i = 0; i < 4; i++) fi[i] = frow[ty * 4 + i];
#pragma unroll
        for (int i = 0; i < 4; i++)
#pragma unroll
            for (int j = 0; j < 4; j++) o[i][j] *= fi[i];
#pragma unroll
        for (int jj = 0; jj < 64; jj++) {
            float4 vv4 = *(const float4*)&KVs[jj * 64 + tx * 4];
            float pi[4];
#pragma unroll
            for (int i = 0; i < 4; i++) pi[i] = Ss[(ty * 4 + i) * 64 + jj];
#pragma unroll
            for (int i = 0; i < 4; i++) {
                o[i][0] += pi[i] * vv4.x;
                o[i][1] += pi[i] * vv4.y;
                o[i][2] += pi[i] * vv4.z;
                o[i][3] += pi[i] * vv4.w;
            }
        }
        __syncthreads();
    }

    float inv[4];
#pragma unroll
    for (int i = 0; i < 4; i++) inv[i] = 1.f / lrow[ty * 4 + i];
#pragma unroll
    for (int i = 0; i < 4; i++) {
        int r = t0 + ty * 4 + i;
        float4 ov;
        ov.x = rnd_tf32(o[i][0] * inv[i]); ov.y = rnd_tf32(o[i][1] * inv[i]);
        ov.z = rnd_tf32(o[i][2] * inv[i]); ov.w = rnd_tf32(o[i][3] * inv[i]);
        *(float4*)(ctx + (size_t)(b * TT + r) * DD + h * HSV + tx * 4) = ov;
    }
}

// ---------------- launcher --------------------------------------------------
extern "C" void kernel_launch(void* const* d_in, const int* in_sizes, int n_in,
                              void* d_out, int out_size) {
    const float* x      = (const float*)d_in[0];
    const float* ln1_g  = (const float*)d_in[1];
    const float* ln1_b  = (const float*)d_in[2];
    const float* wq     = (const float*)d_in[3];
    const float* wk     = (const float*)d_in[4];
    const float* wv     = (const float*)d_in[5];
    const float* w_proj = (const float*)d_in[6];
    const float* b_proj = (const float*)d_in[7];
    const float* ln2_g  = (const float*)d_in[8];
    const float* ln2_b  = (const float*)d_in[9];
    const float* w1     = (const float*)d_in[10];
    const float* b1     = (const float*)d_in[11];
    const float* w2     = (const float*)d_in[12];
    const float* b2     = (const float*)d_in[13];
    float* out = (float*)d_out;

    float *xn, *qkv, *ctx, *x1, *hb, *w;
    cudaGetSymbolAddress((void**)&xn,  g_xn);
    cudaGetSymbolAddress((void**)&qkv, g_qkv);
    cudaGetSymbolAddress((void**)&ctx, g_ctx);
    cudaGetSymbolAddress((void**)&x1,  g_x1);
    cudaGetSymbolAddress((void**)&hb,  g_h);
    cudaGetSymbolAddress((void**)&w,   g_w);
    float* wqkv = w;                      // [3072, 1024]
    float* wpro = w + 3 * 1024 * 1024;    // [1024, 1024]
    float* w1t  = w + 4 * 1024 * 1024;    // [4096, 1024]
    float* w2t  = w + 8 * 1024 * 1024;    // [1024, 4096]

    const size_t GSMEM = (size_t)GS * STGF * sizeof(float);   // 110592
    cudaFuncSetAttribute(tc_gemm<false,false,false,false>, cudaFuncAttributeMaxDynamicSharedMemorySize, GSMEM);
    cudaFuncSetAttribute(tc_gemm<true ,false,true ,false>, cudaFuncAttributeMaxDynamicSharedMemorySize, GSMEM);
    cudaFuncSetAttribute(tc_gemm<true ,true ,false,true >, cudaFuncAttributeMaxDynamicSharedMemorySize, GSMEM);
    cudaFuncSetAttribute(attn_kernel, cudaFuncAttributeMaxDynamicSharedMemorySize, 49920);

    dim3 tb(32, 32);
    transpose_qkv<<<dim3(32, 2, 16), tb>>>(wq, wqkv);
    transpose_qkv<<<dim3(32, 2, 16), tb>>>(wk, wqkv + 1024 * 1024);
    transpose_qkv<<<dim3(32, 2, 16), tb>>>(wv, wqkv + 2 * 1024 * 1024);
    transpose_mat<<<dim3(32, 32),  tb>>>(w_proj, wpro, 1024, 1024);
    transpose_mat<<<dim3(128, 32), tb>>>(w1, w1t, 1024, 4096);
    transpose_mat<<<dim3(32, 128), tb>>>(w2, w2t, 4096, 1024);

    // LN1
    ln_kernel<<<BT, 256>>>(x, ln1_g, ln1_b, xn);

    // fused QKV projection: [8192, 3072]
    tc_gemm<false,false,false,false><<<dim3(24, 64), 256, GSMEM>>>(
        xn, wqkv, nullptr, nullptr, qkv, BT, 3 * DD, DD);

    // attention
    attn_kernel<<<dim3(TT / 64, BB * HH), 256, 49920>>>(qkv, ctx);

    // output projection + residual
    tc_gemm<true,false,true,false><<<dim3(8, 64), 256, GSMEM>>>(
        ctx, wpro, b_proj, x, x1, BT, DD, DD);

    // LN2
    ln_kernel<<<BT, 256>>>(x1, ln2_g, ln2_b, xn);

    // FFN
    tc_gemm<true,true,false,true><<<dim3(32, 64), 256, GSMEM>>>(
        xn, w1t, b1, nullptr, hb, BT, FF, DD);
    tc_gemm<true,false,true,false><<<dim3(8, 64), 256, GSMEM>>>(
        hb, w2t, b2, x1, out, BT, DD, FF);
}

// round 4
// speedup vs baseline: 9.0685x; 4.4852x over previous
#include <cuda_runtime.h>
#include <cuda_fp16.h>
#include <math.h>
#include <stdint.h>

#define BB   4
#define TT   2048
#define DD   1024
#define HH   16
#define HSV  64
#define FF   4096
#define BT   (BB*TT)
#define QLD  (3*DD)          // packed qkv row stride (halfs)

// ---------------- scratch (device globals; no runtime allocation) ----------
__device__ __half g_xn [BT*DD];
__device__ __half g_qkv[(size_t)BT*3*DD];
__device__ __half g_ctx[BT*DD];
__device__ float  g_x1 [BT*DD];
__device__ __half g_h  [(size_t)BT*FF];
__device__ __half g_w  [12*1024*1024];   // qkv' 3M | proj' 1M | w1' 4M | w2' 4M

// ---------------- small helpers --------------------------------------------
__device__ __forceinline__ uint32_t s2u(const void* p) {
    return (uint32_t)__cvta_generic_to_shared(p);
}
__device__ __forceinline__ uint32_t pkh2(float a, float b) {
    __half2 h = __floats2half2_rn(a, b);
    return *reinterpret_cast<uint32_t*>(&h);
}
__device__ __forceinline__ void mma_f16(float* c, const uint32_t* a, const uint32_t* b) {
    asm volatile(
        "mma.sync.aligned.m16n8k16.row.col.f32.f16.f16.f32 "
        "{%0,%1,%2,%3}, {%4,%5,%6,%7}, {%8,%9}, {%0,%1,%2,%3};"
        : "+f"(c[0]), "+f"(c[1]), "+f"(c[2]), "+f"(c[3])
        : "r"(a[0]), "r"(a[1]), "r"(a[2]), "r"(a[3]), "r"(b[0]), "r"(b[1]));
}
#define LDSM4(r0,r1,r2,r3,a) \
    asm volatile("ldmatrix.sync.aligned.m8n8.x4.shared.b16 {%0,%1,%2,%3}, [%4];" \
        : "=r"(r0),"=r"(r1),"=r"(r2),"=r"(r3) : "r"(a))
#define LDSM4T(r0,r1,r2,r3,a) \
    asm volatile("ldmatrix.sync.aligned.m8n8.x4.trans.shared.b16 {%0,%1,%2,%3}, [%4];" \
        : "=r"(r0),"=r"(r1),"=r"(r2),"=r"(r3) : "r"(a))
__device__ __forceinline__ void cpa(uint32_t dst, const void* src) {
    asm volatile("cp.async.cg.shared.global [%0], [%1], 16;"
                 :: "r"(dst), "l"(src) : "memory");
}
#define CP_COMMIT() asm volatile("cp.async.commit_group;" ::: "memory")
template<int N> __device__ __forceinline__ void cp_wait() {
    asm volatile("cp.async.wait_group %0;" :: "n"(N) : "memory");
}

// ---------------- weight repack kernels (fp32 -> fp16) ----------------------
// wq/wk/wv: [H, D, HS] -> out rows n=h*64+j, cols d  ([1024,1024] K-major)
__global__ void transpose_qkv(const float* __restrict__ w, __half* __restrict__ out) {
    __shared__ float sm_[32][33];
    int d0 = blockIdx.x * 32, j0 = blockIdx.y * 32, h = blockIdx.z;
    sm_[threadIdx.y][threadIdx.x] =
        w[((size_t)h * DD + d0 + threadIdx.y) * HSV + j0 + threadIdx.x];
    __syncthreads();
    out[(size_t)(h * HSV + j0 + threadIdx.y) * DD + d0 + threadIdx.x] =
        __float2half_rn(sm_[threadIdx.x][threadIdx.y]);
}
// in [K, N] row-major fp32 -> out [N, K] row-major fp16
__global__ void transpose_mat(const float* __restrict__ in, __half* __restrict__ out,
                              int K, int N) {
    __shared__ float sm_[32][33];
    int n0 = blockIdx.x * 32, k0 = blockIdx.y * 32;
    sm_[threadIdx.y][threadIdx.x] = in[(size_t)(k0 + threadIdx.y) * N + n0 + threadIdx.x];
    __syncthreads();
    out[(size_t)(n0 + threadIdx.y) * K + k0 + threadIdx.x] =
        __float2half_rn(sm_[threadIdx.x][threadIdx.y]);
}

// ---------------- layernorm (fp32 in, fp16 out) -----------------------------
__global__ void ln_kernel(const float* __restrict__ x, const float* __restrict__ g,
                          const float* __restrict__ b, __half* __restrict__ out) {
    int row = blockIdx.x;
    const float* xr = x + (size_t)row * DD;
    float vv[4];
    float s = 0.f, sq = 0.f;
#pragma unroll
    for (int i = 0; i < 4; i++) {
        float t = xr[threadIdx.x + i * 256];
        vv[i] = t; s += t; sq += t * t;
    }
    __shared__ float red[64];
#pragma unroll
    for (int o = 16; o > 0; o >>= 1) {
        s  += __shfl_xor_sync(0xffffffffu, s, o);
        sq += __shfl_xor_sync(0xffffffffu, sq, o);
    }
    int warp = threadIdx.x >> 5, lane = threadIdx.x & 31;
    if (lane == 0) { red[warp] = s; red[warp + 8] = sq; }
    __syncthreads();
    if (threadIdx.x < 32) {
        float ss = (threadIdx.x < 8) ? red[threadIdx.x] : 0.f;
        float qq = (threadIdx.x < 8) ? red[threadIdx.x + 8] : 0.f;
#pragma unroll
        for (int o = 4; o > 0; o >>= 1) {
            ss += __shfl_xor_sync(0xffffffffu, ss, o);
            qq += __shfl_xor_sync(0xffffffffu, qq, o);
        }
        if (threadIdx.x == 0) { red[32] = ss; red[33] = qq; }
    }
    __syncthreads();
    float mean = red[32] * (1.f / DD);
    float var  = red[33] * (1.f / DD) - mean * mean;
    float inv  = rsqrtf(var + 1e-5f);
#pragma unroll
    for (int i = 0; i < 4; i++) {
        int c = threadIdx.x + i * 256;
        out[(size_t)row * DD + c] = __float2half_rn((vv[i] - mean) * inv * g[c] + b[c]);
    }
}

// ---------------- fp16 mma GEMM: C = A[MxK] @ Bt[NxK]^T ---------------------
// 128x128 tile, BK=32, 3-stage cp.async, 8 warps (2x4), 64x32 warp tiles.
#define GS 3
#define SPITCH 40                    // halfs per 32-col row (80B, LDSM-conflict-free)
#define STGH (2*128*SPITCH)          // halfs per stage (A+B)
#define ATILEH (128*SPITCH)

__device__ __forceinline__ void ld_stage(__half* sA, const __half* Ag, const __half* Bg,
                                         int K, int tid) {
#pragma unroll
    for (int i = 0; i < 2; i++) {
        int j = tid + (i << 8);
        int r = j >> 2, q = j & 3;
        cpa(s2u(sA + r * SPITCH + q * 8), Ag + (size_t)r * K + q * 8);
    }
    __half* sB = sA + ATILEH;
#pragma unroll
    for (int i = 0; i < 2; i++) {
        int j = tid + (i << 8);
        int r = j >> 2, q = j & 3;
        cpa(s2u(sB + r * SPITCH + q * 8), Bg + (size_t)r * K + q * 8);
    }
}

template<bool HOUT, bool BIAS, bool RELU, bool RES>
__global__ __launch_bounds__(256, 2)
void tc_gemm(const __half* __restrict__ A, const __half* __restrict__ Bt,
             const float* __restrict__ bias, const float* __restrict__ res,
             void* __restrict__ Cv, int M, int N, int K) {
    extern __shared__ __half sm[];
    int tid = threadIdx.x, wid = tid >> 5, lane = tid & 31;
    int wm = wid >> 2, wn = wid & 3;          // warp grid 2(M) x 4(N)
    int g = lane >> 2, tig = lane & 3;
    int n0 = blockIdx.x * 128, m0 = blockIdx.y * 128;

    const __half* Ab = A + (size_t)m0 * K;
    const __half* Bb = Bt + (size_t)n0 * K;
    int nch = K >> 5;

    float acc[4][4][4] = {};

#pragma unroll
    for (int c = 0; c < GS; c++) {
        ld_stage(sm + c * STGH, Ab + c * 32, Bb + c * 32, K, tid);
        CP_COMMIT();
    }

    for (int c = 0; c < nch; c++) {
        cp_wait<GS - 1>();
        __syncthreads();
        __half* sA = sm + (c % GS) * STGH;
        __half* sB = sA + ATILEH;

        uint32_t bk[4][2][2];
#pragma unroll
        for (int j = 0; j < 4; j++) {
            uint32_t a = s2u(sB + (wn * 32 + j * 8 + (lane & 7)) * SPITCH
                             + ((lane >> 3) & 3) * 8);
            LDSM4(bk[j][0][0], bk[j][0][1], bk[j][1][0], bk[j][1][1], a);
        }
#pragma unroll
        for (int kk = 0; kk < 2; kk++) {
            uint32_t af[4][4];
#pragma unroll
            for (int i = 0; i < 4; i++) {
                uint32_t a = s2u(sA + (wm * 64 + i * 16 + (lane & 15)) * SPITCH
                                 + kk * 16 + (lane >> 4) * 8);
                LDSM4(af[i][0], af[i][1], af[i][2], af[i][3], a);
            }
#pragma unroll
            for (int i = 0; i < 4; i++)
#pragma unroll
                for (int j = 0; j < 4; j++)
                    mma_f16(acc[i][j], af[i], bk[j][kk]);
        }
        __syncthreads();
        if (c + GS < nch)
            ld_stage(sA, Ab + (size_t)(c + GS) * 32, Bb + (size_t)(c + GS) * 32, K, tid);
        CP_COMMIT();
    }

    // epilogue
#pragma unroll
    for (int i = 0; i < 4; i++) {
        int m_up = m0 + wm * 64 + i * 16 + g;
#pragma unroll
        for (int j = 0; j < 4; j++) {
            int n = n0 + wn * 32 + j * 8 + 2 * tig;
            float v0 = acc[i][j][0], v1 = acc[i][j][1];
            float v2 = acc[i][j][2], v3 = acc[i][j][3];
            if (BIAS) {
                float2 bv = *(const float2*)(bias + n);
                v0 += bv.x; v1 += bv.y; v2 += bv.x; v3 += bv.y;
            }
            if (RELU) {
                v0 = fmaxf(v0, 0.f); v1 = fmaxf(v1, 0.f);
                v2 = fmaxf(v2, 0.f); v3 = fmaxf(v3, 0.f);
            }
            if (RES) {
                float2 r0 = *(const float2*)(res + (size_t)m_up * N + n);
                float2 r1 = *(const float2*)(res + (size_t)(m_up + 8) * N + n);
                v0 += r0.x; v1 += r0.y; v2 += r1.x; v3 += r1.y;
            }
            if (HOUT) {
                __half* C = (__half*)Cv;
                __half2 h0 = __floats2half2_rn(v0, v1);
                __half2 h1 = __floats2half2_rn(v2, v3);
                *(__half2*)(C + (size_t)m_up * N + n) = h0;
                *(__half2*)(C + (size_t)(m_up + 8) * N + n) = h1;
            } else {
                float* C = (float*)Cv;
                *(float2*)(C + (size_t)m_up * N + n) = make_float2(v0, v1);
                *(float2*)(C + (size_t)(m_up + 8) * N + n) = make_float2(v2, v3);
            }
        }
    }
}

// ---------------- fp16 mma causal flash attention, 64x64 tiles --------------
// qkv fp16: row (b*T+t), stride QLD; q at +h*64, k at +1024+h*64, v at +2048+h*64
#define APITCH 72
__global__ __launch_bounds__(128)
void attn_kernel(const __half* __restrict__ qkv, __half* __restrict__ ctx) {
    __shared__ __half Qs[64 * APITCH];
    __shared__ __half Ks[64 * APITCH];
    __shared__ __half Vs[64 * APITCH];

    int qt = blockIdx.x, bh = blockIdx.y;
    int b = bh >> 4, h = bh & 15;
    int tid = threadIdx.x, w = tid >> 5, lane = tid & 31;
    int g = lane >> 2, t = lane & 3;

    const __half* qb = qkv + ((size_t)(b * TT) + qt * 64) * QLD + h * 64;
    const __half* kb = qkv + (size_t)(b * TT) * QLD + DD + h * 64;
    const __half* vb = kb + DD;

    // load Q tile
#pragma unroll
    for (int i = 0; i < 4; i++) {
        int j = tid + i * 128;
        int r = j >> 3, q = j & 7;
        cpa(s2u(Qs + r * APITCH + q * 8), qb + (size_t)r * QLD + q * 8);
    }
    CP_COMMIT();
    cp_wait<0>();
    __syncthreads();

    uint32_t qf[4][4];
#pragma unroll
    for (int kk = 0; kk < 4; kk++) {
        uint32_t a = s2u(Qs + (w * 16 + (lane & 15)) * APITCH + kk * 16 + (lane >> 4) * 8);
        LDSM4(qf[kk][0], qf[kk][1], qf[kk][2], qf[kk][3], a);
    }

    float o[8][4] = {};
    float m0 = -1e30f, m1 = -1e30f, l0 = 0.f, l1 = 0.f;
    int row0 = qt * 64 + w * 16 + g, row1 = row0 + 8;

    for (int jt = 0; jt <= qt; jt++) {
#pragma unroll
        for (int i = 0; i < 4; i++) {
            int j = tid + i * 128;
            int r = j >> 3, q = j & 7;
            size_t gr = (size_t)(jt * 64 + r) * QLD;
            cpa(s2u(Ks + r * APITCH + q * 8), kb + gr + q * 8);
            cpa(s2u(Vs + r * APITCH + q * 8), vb + gr + q * 8);
        }
        CP_COMMIT();
        cp_wait<0>();
        __syncthreads();

        // S = Q @ K^T
        float s[8][4] = {};
#pragma unroll
        for (int j = 0; j < 8; j++) {
            uint32_t bb[4][2];
            uint32_t a0 = s2u(Ks + (j * 8 + (lane & 7)) * APITCH + ((lane >> 3) & 3) * 8);
            LDSM4(bb[0][0], bb[0][1], bb[1][0], bb[1][1], a0);
            LDSM4(bb[2][0], bb[2][1], bb[3][0], bb[3][1], a0 + 64);  // +32 halfs
#pragma unroll
            for (int kk = 0; kk < 4; kk++) mma_f16(s[j], qf[kk], bb[kk]);
        }

        // scale + causal mask (diag tile only)
        bool diag = (jt == qt);
#pragma unroll
        for (int j = 0; j < 8; j++) {
            s[j][0] *= 0.125f; s[j][1] *= 0.125f;
            s[j][2] *= 0.125f; s[j][3] *= 0.125f;
            if (diag) {
                int c0 = jt * 64 + j * 8 + 2 * t;
                if (c0 > row0)     s[j][0] = -1e30f;
                if (c0 + 1 > row0) s[j][1] = -1e30f;
                if (c0 > row1)     s[j][2] = -1e30f;
                if (c0 + 1 > row1) s[j][3] = -1e30f;
            }
        }

        // online softmax (per 16-row warp slice; quad = row mates)
        float mx0 = -1e30f, mx1 = -1e30f;
#pragma unroll
        for (int j = 0; j < 8; j++) {
            mx0 = fmaxf(mx0, fmaxf(s[j][0], s[j][1]));
            mx1 = fmaxf(mx1, fmaxf(s[j][2], s[j][3]));
        }
        mx0 = fmaxf(mx0, __shfl_xor_sync(0xffffffffu, mx0, 1));
        mx0 = fmaxf(mx0, __shfl_xor_sync(0xffffffffu, mx0, 2));
        mx1 = fmaxf(mx1, __shfl_xor_sync(0xffffffffu, mx1, 1));
        mx1 = fmaxf(mx1, __shfl_xor_sync(0xffffffffu, mx1, 2));
        float mn0 = fmaxf(m0, mx0), mn1 = fmaxf(m1, mx1);
        float f0 = __expf(m0 - mn0), f1 = __expf(m1 - mn1);
        float sum0 = 0.f, sum1 = 0.f;
#pragma unroll
        for (int j = 0; j < 8; j++) {
            s[j][0] = __expf(s[j][0] - mn0);
            s[j][1] = __expf(s[j][1] - mn0);
            s[j][2] = __expf(s[j][2] - mn1);
            s[j][3] = __expf(s[j][3] - mn1);
            sum0 += s[j][0] + s[j][1];
            sum1 += s[j][2] + s[j][3];
        }
        sum0 += __shfl_xor_sync(0xffffffffu, sum0, 1);
        sum0 += __shfl_xor_sync(0xffffffffu, sum0, 2);
        sum1 += __shfl_xor_sync(0xffffffffu, sum1, 1);
        sum1 += __shfl_xor_sync(0xffffffffu, sum1, 2);
        l0 = l0 * f0 + sum0; l1 = l1 * f1 + sum1;
        m0 = mn0; m1 = mn1;
#pragma unroll
        for (int jo = 0; jo < 8; jo++) {
            o[jo][0] *= f0; o[jo][1] *= f0;
            o[jo][2] *= f1; o[jo][3] *= f1;
        }

        // O += P @ V
#pragma unroll
        for (int kk = 0; kk < 4; kk++) {
            uint32_t ap[4];
            ap[0] = pkh2(s[2*kk][0],   s[2*kk][1]);
            ap[1] = pkh2(s[2*kk][2],   s[2*kk][3]);
            ap[2] = pkh2(s[2*kk+1][0], s[2*kk+1][1]);
            ap[3] = pkh2(s[2*kk+1][2], s[2*kk+1][3]);
#pragma unroll
            for (int hb = 0; hb < 4; hb++) {
                uint32_t bv[4];
                uint32_t a = s2u(Vs + (kk * 16 + (lane & 15)) * APITCH
                                 + hb * 16 + (lane >> 4) * 8);
                LDSM4T(bv[0], bv[1], bv[2], bv[3], a);
                mma_f16(o[hb * 2],     ap, bv);
                mma_f16(o[hb * 2 + 1], ap, bv + 2);
            }
        }
        __syncthreads();
    }

    float inv0 = 1.f / l0, inv1 = 1.f / l1;
    __half* c0 = ctx + ((size_t)(b * TT) + row0) * DD + h * 64;
    __half* c1 = ctx + ((size_t)(b * TT) + row1) * DD + h * 64;
#pragma unroll
    for (int jo = 0; jo < 8; jo++) {
        int col = jo * 8 + 2 * t;
        *(__half2*)(c0 + col) = __floats2half2_rn(o[jo][0] * inv0, o[jo][1] * inv0);
        *(__half2*)(c1 + col) = __floats2half2_rn(o[jo][2] * inv1, o[jo][3] * inv1);
    }
}

// ---------------- launcher --------------------------------------------------
extern "C" void kernel_launch(void* const* d_in, const int* in_sizes, int n_in,
                              void* d_out, int out_size) {
    const float* x      = (const float*)d_in[0];
    const float* ln1_g  = (const float*)d_in[1];
    const float* ln1_b  = (const float*)d_in[2];
    const float* wq     = (const float*)d_in[3];
    const float* wk     = (const float*)d_in[4];
    const float* wv     = (const float*)d_in[5];
    const float* w_proj = (const float*)d_in[6];
    const float* b_proj = (const float*)d_in[7];
    const float* ln2_g  = (const float*)d_in[8];
    const float* ln2_b  = (const float*)d_in[9];
    const float* w1     = (const float*)d_in[10];
    const float* b1     = (const float*)d_in[11];
    const float* w2     = (const float*)d_in[12];
    const float* b2     = (const float*)d_in[13];
    float* out = (float*)d_out;

    __half *xn, *qkv, *ctx, *hb, *w;
    float *x1;
    cudaGetSymbolAddress((void**)&xn,  g_xn);
    cudaGetSymbolAddress((void**)&qkv, g_qkv);
    cudaGetSymbolAddress((void**)&ctx, g_ctx);
    cudaGetSymbolAddress((void**)&x1,  g_x1);
    cudaGetSymbolAddress((void**)&hb,  g_h);
    cudaGetSymbolAddress((void**)&w,   g_w);
    __half* wqkv = w;                      // [3072, 1024]
    __half* wpro = w + 3 * 1024 * 1024;    // [1024, 1024]
    __half* w1t  = w + 4 * 1024 * 1024;    // [4096, 1024]
    __half* w2t  = w + 8 * 1024 * 1024;    // [1024, 4096]

    const size_t GSMEM = (size_t)GS * STGH * sizeof(__half);   // 61440
    cudaFuncSetAttribute(tc_gemm<true ,false,false,false>, cudaFuncAttributeMaxDynamicSharedMemorySize, GSMEM);
    cudaFuncSetAttribute(tc_gemm<false,true ,false,true >, cudaFuncAttributeMaxDynamicSharedMemorySize, GSMEM);
    cudaFuncSetAttribute(tc_gemm<true ,true ,true ,false>, cudaFuncAttributeMaxDynamicSharedMemorySize, GSMEM);

    dim3 tb(32, 32);
    transpose_qkv<<<dim3(32, 2, 16), tb>>>(wq, wqkv);
    transpose_qkv<<<dim3(32, 2, 16), tb>>>(wk, wqkv + 1024 * 1024);
    transpose_qkv<<<dim3(32, 2, 16), tb>>>(wv, wqkv + 2 * 1024 * 1024);
    transpose_mat<<<dim3(32, 32),  tb>>>(w_proj, wpro, 1024, 1024);
    transpose_mat<<<dim3(128, 32), tb>>>(w1, w1t, 1024, 4096);
    transpose_mat<<<dim3(32, 128), tb>>>(w2, w2t, 4096, 1024);

    // LN1
    ln_kernel<<<BT, 256>>>(x, ln1_g, ln1_b, xn);

    // fused QKV projection: [8192, 3072] fp16 out
    tc_gemm<true,false,false,false><<<dim3(24, 64), 256, GSMEM>>>(
        xn, wqkv, nullptr, nullptr, qkv, BT, 3 * DD, DD);

    // attention (fp16 mma flash)
    attn_kernel<<<dim3(TT / 64, BB * HH), 128>>>(qkv, ctx);

    // output projection + bias + residual -> x1 fp32
    tc_gemm<false,true,false,true><<<dim3(8, 64), 256, GSMEM>>>(
        ctx, wpro, b_proj, x, x1, BT, DD, DD);

    // LN2
    ln_kernel<<<BT, 256>>>(x1, ln2_g, ln2_b, xn);

    // FFN1: relu(xn @ w1 + b1) -> h fp16
    tc_gemm<true,true,true,false><<<dim3(32, 64), 256, GSMEM>>>(
        xn, w1t, b1, nullptr, hb, BT, FF, DD);
    // FFN2: h @ w2 + b2 + x1 -> out fp32
    tc_gemm<false,true,false,true><<<dim3(8, 64), 256, GSMEM>>>(
        hb, w2t, b2, x1, out, BT, DD, FF);
}